// round 1
// baseline (speedup 1.0000x reference)
#include <cuda_runtime.h>
#include <cuda_bf16.h>
#include <math_constants.h>

// Problem constants
#define NN   10000
#define FF   128
#define DEG  32
#define OUTF 128

// Scratch (allocation-free rule: __device__ globals)
// CP layout: [i][c], c in [0,1024): c<512 -> C_m (center proj), c>=512 -> P_m (neighbor proj)
//   within each half: m*128 + f, m in {sum, mean, max, min}
__device__ float g_CP[(size_t)NN * 1024];
// H layout: [i][512] = concat(agg_sum, agg_mean, agg_max, agg_min)
__device__ float g_H[(size_t)NN * 512];

// ---------------------------------------------------------------------------
// Kernel 1: CP = X @ Wbig   (M=10000, K=128, N=1024)
// Column c maps to mask m=(c>>7)&3; row offset +128 if c>=512 (neighbor half).
// Tiled SGEMM: BM=BN=64, BK=32, 256 threads, 4x4 per thread.
// ---------------------------------------------------------------------------
__global__ __launch_bounds__(256) void gemm_cp_kernel(
    const float* __restrict__ X,
    const float* __restrict__ Wsum, const float* __restrict__ Wmean,
    const float* __restrict__ Wmax, const float* __restrict__ Wmin)
{
    __shared__ float As[32][65];   // [k][row], padded
    __shared__ float Bs[32][64];   // [k][col]

    const int colBase = blockIdx.x * 64;
    const int rowBase = blockIdx.y * 64;

    const int m = (colBase >> 7) & 3;
    const float* __restrict__ Wm = (m == 0) ? Wsum : (m == 1) ? Wmean : (m == 2) ? Wmax : Wmin;
    const int rowOff = (colBase >= 512) ? 128 : 0;
    const int f0 = colBase & 127;

    const int tid = threadIdx.x;
    const int tx = tid & 15;   // col group
    const int ty = tid >> 4;   // row group

    float acc[4][4];
#pragma unroll
    for (int a = 0; a < 4; a++)
#pragma unroll
        for (int b = 0; b < 4; b++) acc[a][b] = 0.f;

    for (int kb = 0; kb < 128; kb += 32) {
        // Load A tile: 64 rows x 32 k, coalesced along k
#pragma unroll
        for (int it = 0; it < 8; it++) {
            int idx = tid + it * 256;
            int k = idx & 31;
            int r = idx >> 5;
            int grow = rowBase + r;
            As[k][r] = (grow < NN) ? X[grow * 128 + kb + k] : 0.f;
        }
        // Load B tile: 32 k x 64 cols, coalesced along col
#pragma unroll
        for (int it = 0; it < 8; it++) {
            int idx = tid + it * 256;
            int n = idx & 63;
            int k = idx >> 6;
            Bs[k][n] = Wm[(rowOff + kb + k) * 128 + f0 + n];
        }
        __syncthreads();

#pragma unroll
        for (int k = 0; k < 32; k++) {
            float a0 = As[k][ty * 4 + 0];
            float a1 = As[k][ty * 4 + 1];
            float a2 = As[k][ty * 4 + 2];
            float a3 = As[k][ty * 4 + 3];
            float4 b = *(const float4*)&Bs[k][tx * 4];
            acc[0][0] += a0 * b.x; acc[0][1] += a0 * b.y; acc[0][2] += a0 * b.z; acc[0][3] += a0 * b.w;
            acc[1][0] += a1 * b.x; acc[1][1] += a1 * b.y; acc[1][2] += a1 * b.z; acc[1][3] += a1 * b.w;
            acc[2][0] += a2 * b.x; acc[2][1] += a2 * b.y; acc[2][2] += a2 * b.z; acc[2][3] += a2 * b.w;
            acc[3][0] += a3 * b.x; acc[3][1] += a3 * b.y; acc[3][2] += a3 * b.z; acc[3][3] += a3 * b.w;
        }
        __syncthreads();
    }

#pragma unroll
    for (int a = 0; a < 4; a++) {
        int grow = rowBase + ty * 4 + a;
        if (grow < NN) {
            float4 v = make_float4(acc[a][0], acc[a][1], acc[a][2], acc[a][3]);
            *(float4*)&g_CP[(size_t)grow * 1024 + colBase + tx * 4] = v;
        }
    }
}

// ---------------------------------------------------------------------------
// Kernel 2: per-node aggregation. 1 warp per node, float4 per lane (128 feats).
// ---------------------------------------------------------------------------
__device__ __forceinline__ float sigf(float a) {
    return __fdividef(1.0f, 1.0f + __expf(-a));
}
__device__ __forceinline__ float4 add4(float4 a, float4 b) {
    return make_float4(a.x + b.x, a.y + b.y, a.z + b.z, a.w + b.w);
}
__device__ __forceinline__ float4 max4(float4 a, float4 b) {
    return make_float4(fmaxf(a.x, b.x), fmaxf(a.y, b.y), fmaxf(a.z, b.z), fmaxf(a.w, b.w));
}
__device__ __forceinline__ float4 min4(float4 a, float4 b) {
    return make_float4(fminf(a.x, b.x), fminf(a.y, b.y), fminf(a.z, b.z), fminf(a.w, b.w));
}
__device__ __forceinline__ float4 sigmul4(float4 c, float4 p, float4 xj) {
    return make_float4(sigf(c.x + p.x) * xj.x,
                       sigf(c.y + p.y) * xj.y,
                       sigf(c.z + p.z) * xj.z,
                       sigf(c.w + p.w) * xj.w);
}

__global__ __launch_bounds__(128) void agg_kernel(
    const float* __restrict__ x, const int* __restrict__ nbr)
{
    const int warp = threadIdx.x >> 5;
    const int lane = threadIdx.x & 31;
    const int i = blockIdx.x * 4 + warp;
    if (i >= NN) return;

    const int jl = nbr[i * DEG + lane];   // lane d holds neighbor d's index

    const float4* __restrict__ x4  = (const float4*)x;
    const float4* __restrict__ CP4 = (const float4*)g_CP;

    const float4 xi = x4[i * 32 + lane];
    const size_t cb = (size_t)i * 256;
    const float4 c0 = CP4[cb + 0  + lane];
    const float4 c1 = CP4[cb + 32 + lane];
    const float4 c2 = CP4[cb + 64 + lane];
    const float4 c3 = CP4[cb + 96 + lane];

    float4 s0 = make_float4(0.f, 0.f, 0.f, 0.f);
    float4 s1 = make_float4(0.f, 0.f, 0.f, 0.f);
    float4 s2 = make_float4(-CUDART_INF_F, -CUDART_INF_F, -CUDART_INF_F, -CUDART_INF_F);
    float4 s3 = make_float4( CUDART_INF_F,  CUDART_INF_F,  CUDART_INF_F,  CUDART_INF_F);

#pragma unroll 4
    for (int d = 0; d < DEG; d++) {
        const int j = __shfl_sync(0xffffffffu, jl, d);
        const float4 xj = x4[j * 32 + lane];
        const size_t pb = (size_t)j * 256 + 128;
        const float4 p0 = CP4[pb + 0  + lane];
        const float4 p1 = CP4[pb + 32 + lane];
        const float4 p2 = CP4[pb + 64 + lane];
        const float4 p3 = CP4[pb + 96 + lane];

        s0 = add4(s0, sigmul4(c0, p0, xj));
        s1 = add4(s1, sigmul4(c1, p1, xj));
        s2 = max4(s2, sigmul4(c2, p2, xj));
        s3 = min4(s3, sigmul4(c3, p3, xj));
    }

    float4* H4 = (float4*)g_H;
    const size_t hb = (size_t)i * 128;
    const float inv_deg = 1.0f / (float)DEG;
    H4[hb + 0  + lane] = add4(xi, s0);
    H4[hb + 32 + lane] = add4(xi, make_float4(s1.x * inv_deg, s1.y * inv_deg,
                                              s1.z * inv_deg, s1.w * inv_deg));
    H4[hb + 64 + lane] = add4(xi, s2);
    H4[hb + 96 + lane] = add4(xi, s3);
}

// ---------------------------------------------------------------------------
// Kernel 3: out = relu(H @ W + bias)   (M=10000, K=512, N=128)
// ---------------------------------------------------------------------------
__global__ __launch_bounds__(256) void gemm_out_kernel(
    const float* __restrict__ W, const float* __restrict__ bias,
    float* __restrict__ out)
{
    __shared__ float As[32][65];
    __shared__ float Bs[32][64];

    const int colBase = blockIdx.x * 64;
    const int rowBase = blockIdx.y * 64;

    const int tid = threadIdx.x;
    const int tx = tid & 15;
    const int ty = tid >> 4;

    float acc[4][4];
#pragma unroll
    for (int a = 0; a < 4; a++)
#pragma unroll
        for (int b = 0; b < 4; b++) acc[a][b] = 0.f;

    for (int kb = 0; kb < 512; kb += 32) {
#pragma unroll
        for (int it = 0; it < 8; it++) {
            int idx = tid + it * 256;
            int k = idx & 31;
            int r = idx >> 5;
            int grow = rowBase + r;
            As[k][r] = (grow < NN) ? g_H[(size_t)grow * 512 + kb + k] : 0.f;
        }
#pragma unroll
        for (int it = 0; it < 8; it++) {
            int idx = tid + it * 256;
            int n = idx & 63;
            int k = idx >> 6;
            Bs[k][n] = W[(kb + k) * 128 + colBase + n];
        }
        __syncthreads();

#pragma unroll
        for (int k = 0; k < 32; k++) {
            float a0 = As[k][ty * 4 + 0];
            float a1 = As[k][ty * 4 + 1];
            float a2 = As[k][ty * 4 + 2];
            float a3 = As[k][ty * 4 + 3];
            float4 b = *(const float4*)&Bs[k][tx * 4];
            acc[0][0] += a0 * b.x; acc[0][1] += a0 * b.y; acc[0][2] += a0 * b.z; acc[0][3] += a0 * b.w;
            acc[1][0] += a1 * b.x; acc[1][1] += a1 * b.y; acc[1][2] += a1 * b.z; acc[1][3] += a1 * b.w;
            acc[2][0] += a2 * b.x; acc[2][1] += a2 * b.y; acc[2][2] += a2 * b.z; acc[2][3] += a2 * b.w;
            acc[3][0] += a3 * b.x; acc[3][1] += a3 * b.y; acc[3][2] += a3 * b.z; acc[3][3] += a3 * b.w;
        }
        __syncthreads();
    }

    const float4 bvec = *(const float4*)&bias[colBase + tx * 4];
#pragma unroll
    for (int a = 0; a < 4; a++) {
        int grow = rowBase + ty * 4 + a;
        if (grow < NN) {
            float4 v = make_float4(fmaxf(acc[a][0] + bvec.x, 0.f),
                                   fmaxf(acc[a][1] + bvec.y, 0.f),
                                   fmaxf(acc[a][2] + bvec.z, 0.f),
                                   fmaxf(acc[a][3] + bvec.w, 0.f));
            *(float4*)&out[(size_t)grow * 128 + colBase + tx * 4] = v;
        }
    }
}

// ---------------------------------------------------------------------------
// Launch
// inputs (metadata order): x, nbr_idx, mask_sum, mask_mean, mask_max, mask_min,
//                          weight, bias
// ---------------------------------------------------------------------------
extern "C" void kernel_launch(void* const* d_in, const int* in_sizes, int n_in,
                              void* d_out, int out_size)
{
    const float* x     = (const float*)d_in[0];
    const int*   nbr   = (const int*)  d_in[1];
    const float* Wsum  = (const float*)d_in[2];
    const float* Wmean = (const float*)d_in[3];
    const float* Wmax  = (const float*)d_in[4];
    const float* Wmin  = (const float*)d_in[5];
    const float* W     = (const float*)d_in[6];
    const float* bias  = (const float*)d_in[7];
    float* out = (float*)d_out;

    // 1) CP = X @ Wbig  (10000 x 1024)
    {
        dim3 grid(1024 / 64, (NN + 63) / 64);
        gemm_cp_kernel<<<grid, 256>>>(x, Wsum, Wmean, Wmax, Wmin);
    }
    // 2) per-node aggregation -> H (10000 x 512)
    {
        dim3 grid((NN + 3) / 4);
        agg_kernel<<<grid, 128>>>(x, nbr);
    }
    // 3) out = relu(H @ W + bias)  (10000 x 128)
    {
        dim3 grid(128 / 64, (NN + 63) / 64);
        gemm_out_kernel<<<grid, 256>>>(W, bias, out);
    }
}

// round 2
// speedup vs baseline: 1.1479x; 1.1479x over previous
#include <cuda_runtime.h>
#include <cuda_bf16.h>
#include <math_constants.h>

#define NN   10000
#define FF   128
#define DEG  32
#define OUTF 128

// Scratch (__device__ globals; no allocation allowed)
__device__ float         g_C[(size_t)NN * 512];   // center projections, fp32 [i][m*128+f]
__device__ __nv_bfloat16 g_P[(size_t)NN * 512];   // neighbor projections, bf16 [j][m*128+f]
__device__ float         g_H[(size_t)NN * 512];   // concat(agg_sum,mean,max,min)

// ---------------------------------------------------------------------------
// Kernel 1: CP = X @ Wbig (M=10000, K=128, N=1024).
// BM=128, BN=64, BK=16, 256 threads, 8x4 per thread.
// cols <512 -> g_C fp32 ; cols >=512 -> g_P bf16
// ---------------------------------------------------------------------------
__global__ __launch_bounds__(256) void gemm_cp_kernel(
    const float* __restrict__ X,
    const float* __restrict__ Wsum, const float* __restrict__ Wmean,
    const float* __restrict__ Wmax, const float* __restrict__ Wmin)
{
    __shared__ float As[16][132];  // [k][row], padded (132*4=528B row stride, 16B aligned)
    __shared__ float Bs[16][64];   // [k][col]

    const int colBase = blockIdx.x * 64;
    const int rowBase = blockIdx.y * 128;

    const int m = (colBase >> 7) & 3;
    const float* __restrict__ Wm = (m == 0) ? Wsum : (m == 1) ? Wmean : (m == 2) ? Wmax : Wmin;
    const int rowOff = (colBase >= 512) ? 128 : 0;
    const int f0 = colBase & 127;

    const int tid = threadIdx.x;
    const int tx = tid & 15;   // col group (4 cols)
    const int ty = tid >> 4;   // row group (8 rows)

    float acc[8][4];
#pragma unroll
    for (int a = 0; a < 8; a++)
#pragma unroll
        for (int b = 0; b < 4; b++) acc[a][b] = 0.f;

    for (int kb = 0; kb < 128; kb += 16) {
        // A tile: 128 rows x 16 k = 512 float4 loads, 2 per thread
#pragma unroll
        for (int it = 0; it < 2; it++) {
            int v = tid * 2 + it;          // float4 id
            int r = v >> 2;                // row 0..127
            int kq = v & 3;                // float4 within the 16-k strip
            int grow = rowBase + r;
            float4 av = (grow < NN) ? *(const float4*)&X[grow * 128 + kb + kq * 4]
                                    : make_float4(0.f, 0.f, 0.f, 0.f);
            As[kq * 4 + 0][r] = av.x;
            As[kq * 4 + 1][r] = av.y;
            As[kq * 4 + 2][r] = av.z;
            As[kq * 4 + 3][r] = av.w;
        }
        // B tile: 16 k x 64 cols = 256 float4, 1 per thread
        {
            int v = tid;
            int k = v >> 4;                // 0..15
            int n = (v & 15) * 4;          // 0..60
            *(float4*)&Bs[k][n] = *(const float4*)&Wm[(rowOff + kb + k) * 128 + f0 + n];
        }
        __syncthreads();

#pragma unroll
        for (int k = 0; k < 16; k++) {
            float4 a0 = *(const float4*)&As[k][ty * 8 + 0];
            float4 a1 = *(const float4*)&As[k][ty * 8 + 4];
            float4 b  = *(const float4*)&Bs[k][tx * 4];
            float ar[8] = {a0.x, a0.y, a0.z, a0.w, a1.x, a1.y, a1.z, a1.w};
#pragma unroll
            for (int r = 0; r < 8; r++) {
                acc[r][0] += ar[r] * b.x;
                acc[r][1] += ar[r] * b.y;
                acc[r][2] += ar[r] * b.z;
                acc[r][3] += ar[r] * b.w;
            }
        }
        __syncthreads();
    }

    const int colOut = (colBase & 511) + tx * 4;   // column within the 512-wide half
    if (colBase < 512) {
#pragma unroll
        for (int a = 0; a < 8; a++) {
            int grow = rowBase + ty * 8 + a;
            if (grow < NN) {
                *(float4*)&g_C[(size_t)grow * 512 + colOut] =
                    make_float4(acc[a][0], acc[a][1], acc[a][2], acc[a][3]);
            }
        }
    } else {
#pragma unroll
        for (int a = 0; a < 8; a++) {
            int grow = rowBase + ty * 8 + a;
            if (grow < NN) {
                __nv_bfloat162 h0 = __floats2bfloat162_rn(acc[a][0], acc[a][1]);
                __nv_bfloat162 h1 = __floats2bfloat162_rn(acc[a][2], acc[a][3]);
                uint2 pk;
                pk.x = *reinterpret_cast<unsigned int*>(&h0);
                pk.y = *reinterpret_cast<unsigned int*>(&h1);
                *(uint2*)&g_P[(size_t)grow * 512 + colOut] = pk;
            }
        }
    }
}

// ---------------------------------------------------------------------------
// Kernel 2: per-node aggregation. 1 warp/node, float4 per lane.
// sigmoid(a) = 0.5*tanh.approx(a/2)+0.5  (1 MUFU)
// ---------------------------------------------------------------------------
__device__ __forceinline__ float sigf(float a) {
    float t;
    asm("tanh.approx.f32 %0, %1;" : "=f"(t) : "f"(0.5f * a));
    return fmaf(0.5f, t, 0.5f);
}
__device__ __forceinline__ float4 add4(float4 a, float4 b) {
    return make_float4(a.x + b.x, a.y + b.y, a.z + b.z, a.w + b.w);
}
__device__ __forceinline__ float4 max4(float4 a, float4 b) {
    return make_float4(fmaxf(a.x, b.x), fmaxf(a.y, b.y), fmaxf(a.z, b.z), fmaxf(a.w, b.w));
}
__device__ __forceinline__ float4 min4(float4 a, float4 b) {
    return make_float4(fminf(a.x, b.x), fminf(a.y, b.y), fminf(a.z, b.z), fminf(a.w, b.w));
}
__device__ __forceinline__ float4 loadP4(const __nv_bfloat16* __restrict__ p) {
    uint2 pk = *(const uint2*)p;
    __nv_bfloat162 h0 = *reinterpret_cast<__nv_bfloat162*>(&pk.x);
    __nv_bfloat162 h1 = *reinterpret_cast<__nv_bfloat162*>(&pk.y);
    float2 f0 = __bfloat1622float2(h0);
    float2 f1 = __bfloat1622float2(h1);
    return make_float4(f0.x, f0.y, f1.x, f1.y);
}
__device__ __forceinline__ float4 sigmul4(float4 c, float4 p, float4 xj) {
    return make_float4(sigf(c.x + p.x) * xj.x,
                       sigf(c.y + p.y) * xj.y,
                       sigf(c.z + p.z) * xj.z,
                       sigf(c.w + p.w) * xj.w);
}

__global__ __launch_bounds__(128) void agg_kernel(
    const float* __restrict__ x, const int* __restrict__ nbr)
{
    const int warp = threadIdx.x >> 5;
    const int lane = threadIdx.x & 31;
    const int i = blockIdx.x * 4 + warp;
    if (i >= NN) return;

    const int jl = nbr[i * DEG + lane];

    const float4* __restrict__ x4 = (const float4*)x;
    const float4* __restrict__ C4 = (const float4*)g_C;

    const float4 xi = x4[i * 32 + lane];
    const size_t cb = (size_t)i * 128;     // in float4 units (512 floats / 4)
    const float4 c0 = C4[cb + 0  + lane];
    const float4 c1 = C4[cb + 32 + lane];
    const float4 c2 = C4[cb + 64 + lane];
    const float4 c3 = C4[cb + 96 + lane];

    float4 s0 = make_float4(0.f, 0.f, 0.f, 0.f);
    float4 s1 = make_float4(0.f, 0.f, 0.f, 0.f);
    float4 s2 = make_float4(-CUDART_INF_F, -CUDART_INF_F, -CUDART_INF_F, -CUDART_INF_F);
    float4 s3 = make_float4( CUDART_INF_F,  CUDART_INF_F,  CUDART_INF_F,  CUDART_INF_F);

#pragma unroll 4
    for (int d = 0; d < DEG; d++) {
        const int j = __shfl_sync(0xffffffffu, jl, d);
        const float4 xj = x4[j * 32 + lane];
        const __nv_bfloat16* __restrict__ prow = &g_P[(size_t)j * 512 + lane * 4];
        const float4 p0 = loadP4(prow + 0);
        const float4 p1 = loadP4(prow + 128);
        const float4 p2 = loadP4(prow + 256);
        const float4 p3 = loadP4(prow + 384);

        s0 = add4(s0, sigmul4(c0, p0, xj));
        s1 = add4(s1, sigmul4(c1, p1, xj));
        s2 = max4(s2, sigmul4(c2, p2, xj));
        s3 = min4(s3, sigmul4(c3, p3, xj));
    }

    float4* H4 = (float4*)g_H;
    const size_t hb = (size_t)i * 128;
    const float inv_deg = 1.0f / (float)DEG;
    H4[hb + 0  + lane] = add4(xi, s0);
    H4[hb + 32 + lane] = add4(xi, make_float4(s1.x * inv_deg, s1.y * inv_deg,
                                              s1.z * inv_deg, s1.w * inv_deg));
    H4[hb + 64 + lane] = add4(xi, s2);
    H4[hb + 96 + lane] = add4(xi, s3);
}

// ---------------------------------------------------------------------------
// Kernel 3: out = relu(H @ W + bias) (M=10000, K=512, N=128)
// BM=128, BN=64, BK=16, 256 threads, 8x4 per thread.
// ---------------------------------------------------------------------------
__global__ __launch_bounds__(256) void gemm_out_kernel(
    const float* __restrict__ W, const float* __restrict__ bias,
    float* __restrict__ out)
{
    __shared__ float As[16][132];
    __shared__ float Bs[16][64];

    const int colBase = blockIdx.x * 64;
    const int rowBase = blockIdx.y * 128;

    const int tid = threadIdx.x;
    const int tx = tid & 15;
    const int ty = tid >> 4;

    float acc[8][4];
#pragma unroll
    for (int a = 0; a < 8; a++)
#pragma unroll
        for (int b = 0; b < 4; b++) acc[a][b] = 0.f;

    for (int kb = 0; kb < 512; kb += 16) {
#pragma unroll
        for (int it = 0; it < 2; it++) {
            int v = tid * 2 + it;
            int r = v >> 2;
            int kq = v & 3;
            int grow = rowBase + r;
            float4 av = (grow < NN) ? *(const float4*)&g_H[(size_t)grow * 512 + kb + kq * 4]
                                    : make_float4(0.f, 0.f, 0.f, 0.f);
            As[kq * 4 + 0][r] = av.x;
            As[kq * 4 + 1][r] = av.y;
            As[kq * 4 + 2][r] = av.z;
            As[kq * 4 + 3][r] = av.w;
        }
        {
            int v = tid;
            int k = v >> 4;
            int n = (v & 15) * 4;
            *(float4*)&Bs[k][n] = *(const float4*)&W[(kb + k) * 128 + colBase + n];
        }
        __syncthreads();

#pragma unroll
        for (int k = 0; k < 16; k++) {
            float4 a0 = *(const float4*)&As[k][ty * 8 + 0];
            float4 a1 = *(const float4*)&As[k][ty * 8 + 4];
            float4 b  = *(const float4*)&Bs[k][tx * 4];
            float ar[8] = {a0.x, a0.y, a0.z, a0.w, a1.x, a1.y, a1.z, a1.w};
#pragma unroll
            for (int r = 0; r < 8; r++) {
                acc[r][0] += ar[r] * b.x;
                acc[r][1] += ar[r] * b.y;
                acc[r][2] += ar[r] * b.z;
                acc[r][3] += ar[r] * b.w;
            }
        }
        __syncthreads();
    }

    const float4 bvec = *(const float4*)&bias[colBase + tx * 4];
#pragma unroll
    for (int a = 0; a < 8; a++) {
        int grow = rowBase + ty * 8 + a;
        if (grow < NN) {
            float4 v = make_float4(fmaxf(acc[a][0] + bvec.x, 0.f),
                                   fmaxf(acc[a][1] + bvec.y, 0.f),
                                   fmaxf(acc[a][2] + bvec.z, 0.f),
                                   fmaxf(acc[a][3] + bvec.w, 0.f));
            *(float4*)&out[(size_t)grow * 128 + colBase + tx * 4] = v;
        }
    }
}

// ---------------------------------------------------------------------------
extern "C" void kernel_launch(void* const* d_in, const int* in_sizes, int n_in,
                              void* d_out, int out_size)
{
    const float* x     = (const float*)d_in[0];
    const int*   nbr   = (const int*)  d_in[1];
    const float* Wsum  = (const float*)d_in[2];
    const float* Wmean = (const float*)d_in[3];
    const float* Wmax  = (const float*)d_in[4];
    const float* Wmin  = (const float*)d_in[5];
    const float* W     = (const float*)d_in[6];
    const float* bias  = (const float*)d_in[7];
    float* out = (float*)d_out;

    {
        dim3 grid(1024 / 64, (NN + 127) / 128);
        gemm_cp_kernel<<<grid, 256>>>(x, Wsum, Wmean, Wmax, Wmin);
    }
    {
        dim3 grid((NN + 3) / 4);
        agg_kernel<<<grid, 128>>>(x, nbr);
    }
    {
        dim3 grid(128 / 64, (NN + 127) / 128);
        gemm_out_kernel<<<grid, 256>>>(W, bias, out);
    }
}

// round 4
// speedup vs baseline: 2.0784x; 1.8106x over previous
#include <cuda_runtime.h>
#include <cuda_bf16.h>
#include <math_constants.h>
#include <cstdint>

#define NN   10000
#define FF   128
#define DEG  32
#define OUTF 128

// ---------------------------------------------------------------------------
// Scratch (__device__ globals; no allocation allowed)
// ---------------------------------------------------------------------------
__device__ float         g_C[(size_t)NN * 512];    // center projections fp32 [i][m*128+f]
__device__ __nv_bfloat16 g_P[(size_t)NN * 512];    // neighbor projections bf16 [j][m*128+f]
__device__ float         g_H[(size_t)NN * 512];    // concat(agg_sum,mean,max,min)
__device__ __nv_bfloat16 g_Xb[(size_t)NN * 128];   // X in bf16
__device__ __nv_bfloat16 g_Wb[(size_t)1024 * 128]; // Wbig transposed: [n][k]

// ---------------------------------------------------------------------------
// Helpers
// ---------------------------------------------------------------------------
__device__ __forceinline__ uint32_t smem_u32(const void* p) {
    uint32_t a;
    asm("{ .reg .u64 t; cvta.to.shared.u64 t, %1; cvt.u32.u64 %0, t; }" : "=r"(a) : "l"(p));
    return a;
}
__device__ __forceinline__ void ldmatrix_x4(uint32_t* r, uint32_t addr) {
    asm volatile("ldmatrix.sync.aligned.m8n8.x4.shared.b16 {%0,%1,%2,%3}, [%4];"
                 : "=r"(r[0]), "=r"(r[1]), "=r"(r[2]), "=r"(r[3]) : "r"(addr));
}
__device__ __forceinline__ void ldmatrix_x2(uint32_t* r, uint32_t addr) {
    asm volatile("ldmatrix.sync.aligned.m8n8.x2.shared.b16 {%0,%1}, [%2];"
                 : "=r"(r[0]), "=r"(r[1]) : "r"(addr));
}
__device__ __forceinline__ void mma_bf16(float* c, const uint32_t* a, const uint32_t* b) {
    asm volatile(
        "mma.sync.aligned.m16n8k16.row.col.f32.bf16.bf16.f32 "
        "{%0,%1,%2,%3}, {%4,%5,%6,%7}, {%8,%9}, {%0,%1,%2,%3};"
        : "+f"(c[0]), "+f"(c[1]), "+f"(c[2]), "+f"(c[3])
        : "r"(a[0]), "r"(a[1]), "r"(a[2]), "r"(a[3]), "r"(b[0]), "r"(b[1]));
}
__device__ __forceinline__ void mma_tf32(float* c, const uint32_t* a, const uint32_t* b) {
    asm volatile(
        "mma.sync.aligned.m16n8k8.row.col.f32.tf32.tf32.f32 "
        "{%0,%1,%2,%3}, {%4,%5,%6,%7}, {%8,%9}, {%0,%1,%2,%3};"
        : "+f"(c[0]), "+f"(c[1]), "+f"(c[2]), "+f"(c[3])
        : "r"(a[0]), "r"(a[1]), "r"(a[2]), "r"(a[3]), "r"(b[0]), "r"(b[1]));
}
__device__ __forceinline__ uint32_t f2tf32(float f) {
    uint32_t r;
    asm("cvt.rna.tf32.f32 %0, %1;" : "=r"(r) : "f"(f));
    return r;
}

// ===========================================================================
// Kernel 0: prep — X -> bf16; Wb[n][k] = transposed Wbig in bf16
// ===========================================================================
__global__ __launch_bounds__(256) void prep_kernel(
    const float* __restrict__ X,
    const float* __restrict__ Wsum, const float* __restrict__ Wmean,
    const float* __restrict__ Wmax, const float* __restrict__ Wmin)
{
    const int tid = blockIdx.x * blockDim.x + threadIdx.x;
    const int stride = gridDim.x * blockDim.x;

    const float4* X4 = (const float4*)X;
    for (int v = tid; v < NN * 128 / 4; v += stride) {
        float4 f = X4[v];
        __nv_bfloat162 h0 = __floats2bfloat162_rn(f.x, f.y);
        __nv_bfloat162 h1 = __floats2bfloat162_rn(f.z, f.w);
        uint2 pk;
        pk.x = *reinterpret_cast<unsigned int*>(&h0);
        pk.y = *reinterpret_cast<unsigned int*>(&h1);
        *(uint2*)&g_Xb[(size_t)v * 4] = pk;
    }

    for (int v = tid; v < 1024 * 32; v += stride) {
        int n  = v >> 5;
        int k4 = (v & 31) * 4;
        int m  = (n >> 7) & 3;
        const float* __restrict__ Wm = (m == 0) ? Wsum : (m == 1) ? Wmean : (m == 2) ? Wmax : Wmin;
        int rowOff = (n >= 512) ? 128 : 0;
        int f = n & 127;
        float a0 = Wm[(rowOff + k4 + 0) * 128 + f];
        float a1 = Wm[(rowOff + k4 + 1) * 128 + f];
        float a2 = Wm[(rowOff + k4 + 2) * 128 + f];
        float a3 = Wm[(rowOff + k4 + 3) * 128 + f];
        __nv_bfloat162 h0 = __floats2bfloat162_rn(a0, a1);
        __nv_bfloat162 h1 = __floats2bfloat162_rn(a2, a3);
        uint2 pk;
        pk.x = *reinterpret_cast<unsigned int*>(&h0);
        pk.y = *reinterpret_cast<unsigned int*>(&h1);
        *(uint2*)&g_Wb[(size_t)n * 128 + k4] = pk;
    }
}

// ===========================================================================
// Kernel 1: CP = Xb @ Wb^T via bf16 mma.sync (M=10000, N=1024, K=128)
// CTA tile 128x128, K=128 resident. 8 warps (4m x 2n), warp tile 32x64.
// ===========================================================================
#define CP_STRIDE 136   // bf16 elems per smem row (128 + 8 pad)

__global__ __launch_bounds__(256) void gemm_cp_mma_kernel()
{
    extern __shared__ char smem[];
    __nv_bfloat16* Xs = (__nv_bfloat16*)smem;                          // [128][136]
    __nv_bfloat16* Ws = (__nv_bfloat16*)(smem + 128 * CP_STRIDE * 2);  // [128][136]

    const int tid  = threadIdx.x;
    const int lane = tid & 31;
    const int wid  = tid >> 5;
    const int warpM = wid >> 1;   // 0..3 -> m offset *32
    const int warpN = wid & 1;    // 0..1 -> n offset *64

    const int nBase   = blockIdx.x * 128;
    const int rowBase = blockIdx.y * 128;

    // Load A tile (128 rows x 128 k)
    for (int v = tid; v < 2048; v += 256) {
        int r = v >> 4, q = v & 15;
        int grow = rowBase + r;
        uint4 val = make_uint4(0u, 0u, 0u, 0u);
        if (grow < NN) val = *(const uint4*)&g_Xb[(size_t)grow * 128 + q * 8];
        *(uint4*)&Xs[r * CP_STRIDE + q * 8] = val;
    }
    // Load B tile (128 n-rows x 128 k)
    for (int v = tid; v < 2048; v += 256) {
        int n = v >> 4, q = v & 15;
        *(uint4*)&Ws[(size_t)n * CP_STRIDE + q * 8] =
            *(const uint4*)&g_Wb[(size_t)(nBase + n) * 128 + q * 8];
    }
    __syncthreads();

    const uint32_t sXs = smem_u32(Xs);
    const uint32_t sWs = smem_u32(Ws);

    float acc[2][8][4];
#pragma unroll
    for (int mt = 0; mt < 2; mt++)
#pragma unroll
        for (int nt = 0; nt < 8; nt++)
#pragma unroll
            for (int e = 0; e < 4; e++) acc[mt][nt][e] = 0.f;

#pragma unroll
    for (int kb = 0; kb < 128; kb += 16) {
        uint32_t aF[2][4];
#pragma unroll
        for (int mt = 0; mt < 2; mt++) {
            int row = warpM * 32 + mt * 16 + (lane & 15);
            int col = kb + (lane >> 4) * 8;
            ldmatrix_x4(aF[mt], sXs + (row * CP_STRIDE + col) * 2);
        }
        uint32_t bF[8][2];
#pragma unroll
        for (int nt = 0; nt < 8; nt++) {
            int nrow = warpN * 64 + nt * 8 + (lane & 7);
            int col  = kb + ((lane & 15) >> 3) * 8;
            ldmatrix_x2(bF[nt], sWs + (nrow * CP_STRIDE + col) * 2);
        }
#pragma unroll
        for (int mt = 0; mt < 2; mt++)
#pragma unroll
            for (int nt = 0; nt < 8; nt++)
                mma_bf16(acc[mt][nt], aF[mt], bF[nt]);
    }

    // Epilogue: rows r0=base+lane/4, r1=r0+8; cols c=(lane%4)*2
#pragma unroll
    for (int mt = 0; mt < 2; mt++) {
        const int r0 = rowBase + warpM * 32 + mt * 16 + (lane >> 2);
        const int r1 = r0 + 8;
#pragma unroll
        for (int nt = 0; nt < 8; nt++) {
            const int cLoc = warpN * 64 + nt * 8 + (lane & 3) * 2;  // 0..127 within tile
            const int cAbs = nBase + cLoc;
            if (cAbs < 512) {
                if (r0 < NN) *(float2*)&g_C[(size_t)r0 * 512 + cAbs] =
                    make_float2(acc[mt][nt][0], acc[mt][nt][1]);
                if (r1 < NN) *(float2*)&g_C[(size_t)r1 * 512 + cAbs] =
                    make_float2(acc[mt][nt][2], acc[mt][nt][3]);
            } else {
                const int cP = cAbs - 512;
                if (r0 < NN) {
                    __nv_bfloat162 h = __floats2bfloat162_rn(acc[mt][nt][0], acc[mt][nt][1]);
                    *(unsigned int*)&g_P[(size_t)r0 * 512 + cP] = *reinterpret_cast<unsigned int*>(&h);
                }
                if (r1 < NN) {
                    __nv_bfloat162 h = __floats2bfloat162_rn(acc[mt][nt][2], acc[mt][nt][3]);
                    *(unsigned int*)&g_P[(size_t)r1 * 512 + cP] = *reinterpret_cast<unsigned int*>(&h);
                }
            }
        }
    }
}

// ===========================================================================
// Kernel 2: per-node aggregation (unchanged)
// ===========================================================================
__device__ __forceinline__ float sigf(float a) {
    float t;
    asm("tanh.approx.f32 %0, %1;" : "=f"(t) : "f"(0.5f * a));
    return fmaf(0.5f, t, 0.5f);
}
__device__ __forceinline__ float4 add4(float4 a, float4 b) {
    return make_float4(a.x + b.x, a.y + b.y, a.z + b.z, a.w + b.w);
}
__device__ __forceinline__ float4 max4(float4 a, float4 b) {
    return make_float4(fmaxf(a.x, b.x), fmaxf(a.y, b.y), fmaxf(a.z, b.z), fmaxf(a.w, b.w));
}
__device__ __forceinline__ float4 min4(float4 a, float4 b) {
    return make_float4(fminf(a.x, b.x), fminf(a.y, b.y), fminf(a.z, b.z), fminf(a.w, b.w));
}
__device__ __forceinline__ float4 loadP4(const __nv_bfloat16* __restrict__ p) {
    uint2 pk = *(const uint2*)p;
    __nv_bfloat162 h0 = *reinterpret_cast<__nv_bfloat162*>(&pk.x);
    __nv_bfloat162 h1 = *reinterpret_cast<__nv_bfloat162*>(&pk.y);
    float2 f0 = __bfloat1622float2(h0);
    float2 f1 = __bfloat1622float2(h1);
    return make_float4(f0.x, f0.y, f1.x, f1.y);
}
__device__ __forceinline__ float4 sigmul4(float4 c, float4 p, float4 xj) {
    return make_float4(sigf(c.x + p.x) * xj.x,
                       sigf(c.y + p.y) * xj.y,
                       sigf(c.z + p.z) * xj.z,
                       sigf(c.w + p.w) * xj.w);
}

__global__ __launch_bounds__(128) void agg_kernel(
    const float* __restrict__ x, const int* __restrict__ nbr)
{
    const int warp = threadIdx.x >> 5;
    const int lane = threadIdx.x & 31;
    const int i = blockIdx.x * 4 + warp;
    if (i >= NN) return;

    const int jl = nbr[i * DEG + lane];

    const float4* __restrict__ x4 = (const float4*)x;
    const float4* __restrict__ C4 = (const float4*)g_C;

    const float4 xi = x4[i * 32 + lane];
    const size_t cb = (size_t)i * 128;
    const float4 c0 = C4[cb + 0  + lane];
    const float4 c1 = C4[cb + 32 + lane];
    const float4 c2 = C4[cb + 64 + lane];
    const float4 c3 = C4[cb + 96 + lane];

    float4 s0 = make_float4(0.f, 0.f, 0.f, 0.f);
    float4 s1 = make_float4(0.f, 0.f, 0.f, 0.f);
    float4 s2 = make_float4(-CUDART_INF_F, -CUDART_INF_F, -CUDART_INF_F, -CUDART_INF_F);
    float4 s3 = make_float4( CUDART_INF_F,  CUDART_INF_F,  CUDART_INF_F,  CUDART_INF_F);

#pragma unroll 4
    for (int d = 0; d < DEG; d++) {
        const int j = __shfl_sync(0xffffffffu, jl, d);
        const float4 xj = x4[j * 32 + lane];
        const __nv_bfloat16* __restrict__ prow = &g_P[(size_t)j * 512 + lane * 4];
        const float4 p0 = loadP4(prow + 0);
        const float4 p1 = loadP4(prow + 128);
        const float4 p2 = loadP4(prow + 256);
        const float4 p3 = loadP4(prow + 384);

        s0 = add4(s0, sigmul4(c0, p0, xj));
        s1 = add4(s1, sigmul4(c1, p1, xj));
        s2 = max4(s2, sigmul4(c2, p2, xj));
        s3 = min4(s3, sigmul4(c3, p3, xj));
    }

    float4* H4 = (float4*)g_H;
    const size_t hb = (size_t)i * 128;
    const float inv_deg = 1.0f / (float)DEG;
    H4[hb + 0  + lane] = add4(xi, s0);
    H4[hb + 32 + lane] = add4(xi, make_float4(s1.x * inv_deg, s1.y * inv_deg,
                                              s1.z * inv_deg, s1.w * inv_deg));
    H4[hb + 64 + lane] = add4(xi, s2);
    H4[hb + 96 + lane] = add4(xi, s3);
}

// ===========================================================================
// Kernel 3: out = relu(H @ W + bias) via tf32 mma.sync (M=10000, K=512, N=128)
// CTA tile 64x128, BK=32. 8 warps (2m x 4n), warp tile 32x32.
// ===========================================================================
__global__ __launch_bounds__(256) void gemm_out_mma_kernel(
    const float* __restrict__ W, const float* __restrict__ bias,
    float* __restrict__ out)
{
    __shared__ float Hs[64][36];
    __shared__ float Ws[32][136];

    const int tid  = threadIdx.x;
    const int lane = tid & 31;
    const int wid  = tid >> 5;
    const int warpM = wid & 1;    // *32
    const int warpN = wid >> 1;   // *32

    const int rowBase = blockIdx.x * 64;

    float acc[2][4][4];
#pragma unroll
    for (int mt = 0; mt < 2; mt++)
#pragma unroll
        for (int nt = 0; nt < 4; nt++)
#pragma unroll
            for (int e = 0; e < 4; e++) acc[mt][nt][e] = 0.f;

    for (int kb = 0; kb < 512; kb += 32) {
        // Load H chunk (64 rows x 32 k)
#pragma unroll
        for (int v = tid; v < 512; v += 256) {
            int r = v >> 3, q = (v & 7) * 4;
            int grow = rowBase + r;
            float4 h = (grow < NN) ? *(const float4*)&g_H[(size_t)grow * 512 + kb + q]
                                   : make_float4(0.f, 0.f, 0.f, 0.f);
            *(float4*)&Hs[r][q] = h;
        }
        // Load W chunk (32 k x 128 n)
#pragma unroll
        for (int v = tid; v < 1024; v += 256) {
            int k = v >> 5, n = (v & 31) * 4;
            *(float4*)&Ws[k][n] = *(const float4*)&W[(size_t)(kb + k) * 128 + n];
        }
        __syncthreads();

#pragma unroll
        for (int ks = 0; ks < 4; ks++) {
            const int k0 = ks * 8;
            uint32_t aF[2][4];
#pragma unroll
            for (int mt = 0; mt < 2; mt++) {
                int r0 = warpM * 32 + mt * 16 + (lane >> 2);
                int kc = k0 + (lane & 3);
                aF[mt][0] = f2tf32(Hs[r0][kc]);
                aF[mt][1] = f2tf32(Hs[r0 + 8][kc]);
                aF[mt][2] = f2tf32(Hs[r0][kc + 4]);
                aF[mt][3] = f2tf32(Hs[r0 + 8][kc + 4]);
            }
            uint32_t bF[4][2];
#pragma unroll
            for (int nt = 0; nt < 4; nt++) {
                int n0 = warpN * 32 + nt * 8 + (lane >> 2);
                int kc = k0 + (lane & 3);
                bF[nt][0] = f2tf32(Ws[kc][n0]);
                bF[nt][1] = f2tf32(Ws[kc + 4][n0]);
            }
#pragma unroll
            for (int mt = 0; mt < 2; mt++)
#pragma unroll
                for (int nt = 0; nt < 4; nt++)
                    mma_tf32(acc[mt][nt], aF[mt], bF[nt]);
        }
        __syncthreads();
    }

    // Epilogue with bias + relu
#pragma unroll
    for (int mt = 0; mt < 2; mt++) {
        const int r0 = rowBase + warpM * 32 + mt * 16 + (lane >> 2);
        const int r1 = r0 + 8;
#pragma unroll
        for (int nt = 0; nt < 4; nt++) {
            const int c = warpN * 32 + nt * 8 + (lane & 3) * 2;
            const float b0 = bias[c], b1 = bias[c + 1];
            if (r0 < NN) {
                *(float2*)&out[(size_t)r0 * 128 + c] = make_float2(
                    fmaxf(acc[mt][nt][0] + b0, 0.f), fmaxf(acc[mt][nt][1] + b1, 0.f));
            }
            if (r1 < NN) {
                *(float2*)&out[(size_t)r1 * 128 + c] = make_float2(
                    fmaxf(acc[mt][nt][2] + b0, 0.f), fmaxf(acc[mt][nt][3] + b1, 0.f));
            }
        }
    }
}

// ===========================================================================
extern "C" void kernel_launch(void* const* d_in, const int* in_sizes, int n_in,
                              void* d_out, int out_size)
{
    const float* x     = (const float*)d_in[0];
    const int*   nbr   = (const int*)  d_in[1];
    const float* Wsum  = (const float*)d_in[2];
    const float* Wmean = (const float*)d_in[3];
    const float* Wmax  = (const float*)d_in[4];
    const float* Wmin  = (const float*)d_in[5];
    const float* W     = (const float*)d_in[6];
    const float* bias  = (const float*)d_in[7];
    float* out = (float*)d_out;

    const int CP_SMEM = 2 * 128 * CP_STRIDE * 2;  // 69,632 B
    cudaFuncSetAttribute(gemm_cp_mma_kernel,
                         cudaFuncAttributeMaxDynamicSharedMemorySize, CP_SMEM);

    // 0) X -> bf16, transposed Wbig -> bf16
    prep_kernel<<<296, 256>>>(x, Wsum, Wmean, Wmax, Wmin);

    // 1) CP = Xb @ Wb^T (10000 x 1024), bf16 HMMA
    {
        dim3 grid(1024 / 128, (NN + 127) / 128);
        gemm_cp_mma_kernel<<<grid, 256, CP_SMEM>>>();
    }

    // 2) per-node aggregation -> H
    {
        dim3 grid((NN + 3) / 4);
        agg_kernel<<<grid, 128>>>(x, nbr);
    }

    // 3) out = relu(H @ W + bias), tf32 HMMA
    {
        dim3 grid((NN + 63) / 64);
        gemm_out_mma_kernel<<<grid, 256>>>(W, bias, out);
    }
}

// round 6
// speedup vs baseline: 2.1690x; 1.0436x over previous
#include <cuda_runtime.h>
#include <cuda_bf16.h>
#include <math_constants.h>
#include <cstdint>

#define NN   10000
#define FF   128
#define DEG  32
#define OUTF 128

// ---------------------------------------------------------------------------
// Scratch (__device__ globals; no allocation allowed)
// ---------------------------------------------------------------------------
__device__ float         g_C[(size_t)NN * 512];     // 0.5 * center projections, fp32
__device__ __nv_bfloat16 g_P[(size_t)NN * 512];     // 0.5 * neighbor projections, bf16
__device__ __nv_bfloat16 g_Xb[(size_t)NN * 128];    // X in bf16
__device__ __nv_bfloat16 g_Wb[(size_t)1024 * 128];  // Wbig transposed (for gemm_cp)
__device__ __nv_bfloat16 g_A2[(size_t)NN * 1536];   // H split: [2k]=hi,[2k+1]=lo (k<512); [1024+k]=hi
__device__ __nv_bfloat16 g_B2[(size_t)128 * 1536];  // W split: [2k]=[2k+1]=Whi; [1024+k]=Wlo

// ---------------------------------------------------------------------------
// Helpers
// ---------------------------------------------------------------------------
__device__ __forceinline__ uint32_t smem_u32(const void* p) {
    uint32_t a;
    asm("{ .reg .u64 t; cvta.to.shared.u64 t, %1; cvt.u32.u64 %0, t; }" : "=r"(a) : "l"(p));
    return a;
}
__device__ __forceinline__ void ldmatrix_x4(uint32_t* r, uint32_t addr) {
    asm volatile("ldmatrix.sync.aligned.m8n8.x4.shared.b16 {%0,%1,%2,%3}, [%4];"
                 : "=r"(r[0]), "=r"(r[1]), "=r"(r[2]), "=r"(r[3]) : "r"(addr));
}
__device__ __forceinline__ void ldmatrix_x2(uint32_t* r, uint32_t addr) {
    asm volatile("ldmatrix.sync.aligned.m8n8.x2.shared.b16 {%0,%1}, [%2];"
                 : "=r"(r[0]), "=r"(r[1]) : "r"(addr));
}
__device__ __forceinline__ void mma_bf16(float* c, const uint32_t* a, const uint32_t* b) {
    asm volatile(
        "mma.sync.aligned.m16n8k16.row.col.f32.bf16.bf16.f32 "
        "{%0,%1,%2,%3}, {%4,%5,%6,%7}, {%8,%9}, {%0,%1,%2,%3};"
        : "+f"(c[0]), "+f"(c[1]), "+f"(c[2]), "+f"(c[3])
        : "r"(a[0]), "r"(a[1]), "r"(a[2]), "r"(a[3]), "r"(b[0]), "r"(b[1]));
}
__device__ __forceinline__ void cp_async16(uint32_t smaddr, const void* gptr) {
    asm volatile("cp.async.ca.shared.global [%0], [%1], 16;"
                 :: "r"(smaddr), "l"(gptr) : "memory");
}
__device__ __forceinline__ uint32_t pack_bf2(__nv_bfloat16 a, __nv_bfloat16 b) {
    __nv_bfloat162 h; h.x = a; h.y = b;
    return *reinterpret_cast<uint32_t*>(&h);
}
__device__ __forceinline__ void bsplit(float v, __nv_bfloat16& hi, __nv_bfloat16& lo) {
    hi = __float2bfloat16_rn(v);
    lo = __float2bfloat16_rn(v - __bfloat162float(hi));
}

// ===========================================================================
// Kernel 0: prep — X->bf16; Wb (transposed Wbig, bf16); B2 (split W for out-GEMM)
// ===========================================================================
__global__ __launch_bounds__(256) void prep_kernel(
    const float* __restrict__ X,
    const float* __restrict__ Wsum, const float* __restrict__ Wmean,
    const float* __restrict__ Wmax, const float* __restrict__ Wmin,
    const float* __restrict__ W)
{
    const int tid = blockIdx.x * blockDim.x + threadIdx.x;
    const int stride = gridDim.x * blockDim.x;

    const float4* X4 = (const float4*)X;
    for (int v = tid; v < NN * 128 / 4; v += stride) {
        float4 f = X4[v];
        uint2 pk;
        pk.x = pack_bf2(__float2bfloat16_rn(f.x), __float2bfloat16_rn(f.y));
        pk.y = pack_bf2(__float2bfloat16_rn(f.z), __float2bfloat16_rn(f.w));
        *(uint2*)&g_Xb[(size_t)v * 4] = pk;
    }

    for (int v = tid; v < 1024 * 32; v += stride) {
        int n  = v >> 5;
        int k4 = (v & 31) * 4;
        int m  = (n >> 7) & 3;
        const float* __restrict__ Wm = (m == 0) ? Wsum : (m == 1) ? Wmean : (m == 2) ? Wmax : Wmin;
        int rowOff = (n >= 512) ? 128 : 0;
        int f = n & 127;
        float a0 = Wm[(rowOff + k4 + 0) * 128 + f];
        float a1 = Wm[(rowOff + k4 + 1) * 128 + f];
        float a2 = Wm[(rowOff + k4 + 2) * 128 + f];
        float a3 = Wm[(rowOff + k4 + 3) * 128 + f];
        uint2 pk;
        pk.x = pack_bf2(__float2bfloat16_rn(a0), __float2bfloat16_rn(a1));
        pk.y = pack_bf2(__float2bfloat16_rn(a2), __float2bfloat16_rn(a3));
        *(uint2*)&g_Wb[(size_t)n * 128 + k4] = pk;
    }

    // B2: [n][1536]: [2k]=[2k+1]=hi(W[k][n]); [1024+k]=lo
    for (int v = tid; v < 128 * 512; v += stride) {
        int n = v & 127;
        int k = v >> 7;
        float w = W[(size_t)k * 128 + n];
        __nv_bfloat16 hi, lo;
        bsplit(w, hi, lo);
        g_B2[(size_t)n * 1536 + 2 * k]     = hi;
        g_B2[(size_t)n * 1536 + 2 * k + 1] = hi;
        g_B2[(size_t)n * 1536 + 1024 + k]  = lo;
    }
}

// ===========================================================================
// Kernel 1: CP = 0.5 * (Xb @ Wb^T) via bf16 mma (M=10000, N=1024, K=128)
// CTA tile 128x128; 8 warps (4m x 2n), warp tile 32x64.
// ===========================================================================
#define CP_STRIDE 136

__global__ __launch_bounds__(256) void gemm_cp_mma_kernel()
{
    extern __shared__ char smem[];
    __nv_bfloat16* Xs = (__nv_bfloat16*)smem;
    __nv_bfloat16* Ws = (__nv_bfloat16*)(smem + 128 * CP_STRIDE * 2);

    const int tid  = threadIdx.x;
    const int lane = tid & 31;
    const int wid  = tid >> 5;
    const int warpM = wid >> 1;
    const int warpN = wid & 1;

    const int nBase   = blockIdx.x * 128;
    const int rowBase = blockIdx.y * 128;

    for (int v = tid; v < 2048; v += 256) {
        int r = v >> 4, q = v & 15;
        int grow = rowBase + r;
        uint4 val = make_uint4(0u, 0u, 0u, 0u);
        if (grow < NN) val = *(const uint4*)&g_Xb[(size_t)grow * 128 + q * 8];
        *(uint4*)&Xs[r * CP_STRIDE + q * 8] = val;
    }
    for (int v = tid; v < 2048; v += 256) {
        int n = v >> 4, q = v & 15;
        *(uint4*)&Ws[(size_t)n * CP_STRIDE + q * 8] =
            *(const uint4*)&g_Wb[(size_t)(nBase + n) * 128 + q * 8];
    }
    __syncthreads();

    const uint32_t sXs = smem_u32(Xs);
    const uint32_t sWs = smem_u32(Ws);

    float acc[2][8][4];
#pragma unroll
    for (int mt = 0; mt < 2; mt++)
#pragma unroll
        for (int nt = 0; nt < 8; nt++)
#pragma unroll
            for (int e = 0; e < 4; e++) acc[mt][nt][e] = 0.f;

#pragma unroll
    for (int kb = 0; kb < 128; kb += 16) {
        uint32_t aF[2][4];
#pragma unroll
        for (int mt = 0; mt < 2; mt++) {
            int row = warpM * 32 + mt * 16 + (lane & 15);
            int col = kb + (lane >> 4) * 8;
            ldmatrix_x4(aF[mt], sXs + (row * CP_STRIDE + col) * 2);
        }
        uint32_t bF[8][2];
#pragma unroll
        for (int nt = 0; nt < 8; nt++) {
            int nrow = warpN * 64 + nt * 8 + (lane & 7);
            int col  = kb + ((lane & 15) >> 3) * 8;
            ldmatrix_x2(bF[nt], sWs + (nrow * CP_STRIDE + col) * 2);
        }
#pragma unroll
        for (int mt = 0; mt < 2; mt++)
#pragma unroll
            for (int nt = 0; nt < 8; nt++)
                mma_bf16(acc[mt][nt], aF[mt], bF[nt]);
    }

    // Epilogue: store 0.5*value (folds sigmoid's a/2 into the projections)
#pragma unroll
    for (int mt = 0; mt < 2; mt++) {
        const int r0 = rowBase + warpM * 32 + mt * 16 + (lane >> 2);
        const int r1 = r0 + 8;
#pragma unroll
        for (int nt = 0; nt < 8; nt++) {
            const int cLoc = warpN * 64 + nt * 8 + (lane & 3) * 2;
            const int cAbs = nBase + cLoc;
            float v00 = 0.5f * acc[mt][nt][0], v01 = 0.5f * acc[mt][nt][1];
            float v10 = 0.5f * acc[mt][nt][2], v11 = 0.5f * acc[mt][nt][3];
            if (cAbs < 512) {
                if (r0 < NN) *(float2*)&g_C[(size_t)r0 * 512 + cAbs] = make_float2(v00, v01);
                if (r1 < NN) *(float2*)&g_C[(size_t)r1 * 512 + cAbs] = make_float2(v10, v11);
            } else {
                const int cP = cAbs - 512;
                if (r0 < NN)
                    *(uint32_t*)&g_P[(size_t)r0 * 512 + cP] =
                        pack_bf2(__float2bfloat16_rn(v00), __float2bfloat16_rn(v01));
                if (r1 < NN)
                    *(uint32_t*)&g_P[(size_t)r1 * 512 + cP] =
                        pack_bf2(__float2bfloat16_rn(v10), __float2bfloat16_rn(v11));
            }
        }
    }
}

// ===========================================================================
// Kernel 2: per-node aggregation -> A2 (bf16 hi/lo split of H)
// sigmoid(a)*x = fma(tanh.approx(a/2), x/2, x/2); a/2 pre-folded into C,P.
// ===========================================================================
__device__ __forceinline__ float tanha(float a) {
    float t;
    asm("tanh.approx.f32 %0, %1;" : "=f"(t) : "f"(a));
    return t;
}
__device__ __forceinline__ float4 add4(float4 a, float4 b) {
    return make_float4(a.x + b.x, a.y + b.y, a.z + b.z, a.w + b.w);
}
__device__ __forceinline__ float4 max4(float4 a, float4 b) {
    return make_float4(fmaxf(a.x, b.x), fmaxf(a.y, b.y), fmaxf(a.z, b.z), fmaxf(a.w, b.w));
}
__device__ __forceinline__ float4 min4(float4 a, float4 b) {
    return make_float4(fminf(a.x, b.x), fminf(a.y, b.y), fminf(a.z, b.z), fminf(a.w, b.w));
}
__device__ __forceinline__ float4 loadP4(const __nv_bfloat16* __restrict__ p) {
    uint2 pk = *(const uint2*)p;
    __nv_bfloat162 h0 = *reinterpret_cast<__nv_bfloat162*>(&pk.x);
    __nv_bfloat162 h1 = *reinterpret_cast<__nv_bfloat162*>(&pk.y);
    float2 f0 = __bfloat1622float2(h0);
    float2 f1 = __bfloat1622float2(h1);
    return make_float4(f0.x, f0.y, f1.x, f1.y);
}
__device__ __forceinline__ float4 sigmul4(float4 c, float4 p, float4 hx) {
    return make_float4(fmaf(tanha(c.x + p.x), hx.x, hx.x),
                       fmaf(tanha(c.y + p.y), hx.y, hx.y),
                       fmaf(tanha(c.z + p.z), hx.z, hx.z),
                       fmaf(tanha(c.w + p.w), hx.w, hx.w));
}
__device__ __forceinline__ void store_split_group(
    __nv_bfloat16* a2, int koff, float4 v)
{
    __nv_bfloat16 h0, l0, h1, l1, h2, l2, h3, l3;
    bsplit(v.x, h0, l0); bsplit(v.y, h1, l1);
    bsplit(v.z, h2, l2); bsplit(v.w, h3, l3);
    uint4 pk;
    pk.x = pack_bf2(h0, l0); pk.y = pack_bf2(h1, l1);
    pk.z = pack_bf2(h2, l2); pk.w = pack_bf2(h3, l3);
    *(uint4*)&a2[2 * koff] = pk;
    uint2 t;
    t.x = pack_bf2(h0, h1); t.y = pack_bf2(h2, h3);
    *(uint2*)&a2[1024 + koff] = t;
}

__global__ __launch_bounds__(128) void agg_kernel(
    const float* __restrict__ x, const int* __restrict__ nbr)
{
    const int warp = threadIdx.x >> 5;
    const int lane = threadIdx.x & 31;
    const int i = blockIdx.x * 4 + warp;
    if (i >= NN) return;

    const int jl = nbr[i * DEG + lane];

    const float4* __restrict__ x4 = (const float4*)x;
    const float4* __restrict__ C4 = (const float4*)g_C;

    const float4 xi = x4[i * 32 + lane];
    const size_t cb = (size_t)i * 128;
    const float4 c0 = C4[cb + 0  + lane];
    const float4 c1 = C4[cb + 32 + lane];
    const float4 c2 = C4[cb + 64 + lane];
    const float4 c3 = C4[cb + 96 + lane];

    float4 s0 = make_float4(0.f, 0.f, 0.f, 0.f);
    float4 s1 = make_float4(0.f, 0.f, 0.f, 0.f);
    float4 s2 = make_float4(-CUDART_INF_F, -CUDART_INF_F, -CUDART_INF_F, -CUDART_INF_F);
    float4 s3 = make_float4( CUDART_INF_F,  CUDART_INF_F,  CUDART_INF_F,  CUDART_INF_F);

#pragma unroll 4
    for (int d = 0; d < DEG; d++) {
        const int j = __shfl_sync(0xffffffffu, jl, d);
        const float4 xj = x4[j * 32 + lane];
        const float4 hx = make_float4(0.5f * xj.x, 0.5f * xj.y, 0.5f * xj.z, 0.5f * xj.w);
        const __nv_bfloat16* __restrict__ prow = &g_P[(size_t)j * 512 + lane * 4];
        const float4 p0 = loadP4(prow + 0);
        const float4 p1 = loadP4(prow + 128);
        const float4 p2 = loadP4(prow + 256);
        const float4 p3 = loadP4(prow + 384);

        s0 = add4(s0, sigmul4(c0, p0, hx));
        s1 = add4(s1, sigmul4(c1, p1, hx));
        s2 = max4(s2, sigmul4(c2, p2, hx));
        s3 = min4(s3, sigmul4(c3, p3, hx));
    }

    const float inv_deg = 1.0f / (float)DEG;
    float4 h0 = add4(xi, s0);
    float4 h1 = add4(xi, make_float4(s1.x * inv_deg, s1.y * inv_deg,
                                     s1.z * inv_deg, s1.w * inv_deg));
    float4 h2 = add4(xi, s2);
    float4 h3 = add4(xi, s3);

    __nv_bfloat16* a2 = &g_A2[(size_t)i * 1536];
    store_split_group(a2, 0   + lane * 4, h0);
    store_split_group(a2, 128 + lane * 4, h1);
    store_split_group(a2, 256 + lane * 4, h2);
    store_split_group(a2, 384 + lane * 4, h3);
}

// ===========================================================================
// Kernel 3: out = relu(A2 @ B2^T + bias)  (M=10000, N=128, K=1536, bf16 HMMA)
// Tile M=80 x N=128 -> exactly 125 CTAs. cp.async double-buffered, BK=128.
// 8 warps: warp = all 80 rows x 16 cols (mt=5, nt=2).
// ===========================================================================
#define OUT_NKB   12
#define OUT_AST   136                      // smem row stride (bf16 elems)
#define OUT_ABYTES (80  * OUT_AST * 2)     // 21760
#define OUT_BBYTES (128 * OUT_AST * 2)     // 34816
#define OUT_STAGE  (OUT_ABYTES + OUT_BBYTES)
#define OUT_SMEM   (2 * OUT_STAGE)         // 113152

__global__ __launch_bounds__(256) void gemm_out_bsplit_kernel(
    const float* __restrict__ bias, float* __restrict__ out)
{
    extern __shared__ char smem[];
    const uint32_t sbase = smem_u32(smem);
    const int tid  = threadIdx.x;
    const int lane = tid & 31;
    const int wid  = tid >> 5;
    const int rowBase = blockIdx.x * 80;
    const int nbase   = wid * 16;

    float acc[5][2][4];
#pragma unroll
    for (int mt = 0; mt < 5; mt++)
#pragma unroll
        for (int nt = 0; nt < 2; nt++)
#pragma unroll
            for (int e = 0; e < 4; e++) acc[mt][nt][e] = 0.f;

    // ---- async load of one K-chunk (128 elems = 16 quads per row) into stage s ----
    auto issue = [&](int kb, int s) {
        const uint32_t abase = sbase + s * OUT_STAGE;
        for (int v = tid; v < 1280; v += 256) {         // A: 80 rows x 16 quads
            int r = v >> 4, q = v & 15;
            cp_async16(abase + (r * OUT_AST + q * 8) * 2,
                       &g_A2[(size_t)(rowBase + r) * 1536 + kb * 128 + q * 8]);
        }
        const uint32_t bbase = abase + OUT_ABYTES;
        for (int v = tid; v < 2048; v += 256) {         // B: 128 rows x 16 quads
            int n = v >> 4, q = v & 15;
            cp_async16(bbase + (n * OUT_AST + q * 8) * 2,
                       &g_B2[(size_t)n * 1536 + kb * 128 + q * 8]);
        }
        asm volatile("cp.async.commit_group;" ::: "memory");
    };

    issue(0, 0);

#pragma unroll
    for (int kb = 0; kb < OUT_NKB; kb++) {
        if (kb + 1 < OUT_NKB) {
            issue(kb + 1, (kb + 1) & 1);
            asm volatile("cp.async.wait_group 1;" ::: "memory");
        } else {
            asm volatile("cp.async.wait_group 0;" ::: "memory");
        }
        __syncthreads();

        const uint32_t aS = sbase + (kb & 1) * OUT_STAGE;
        const uint32_t bS = aS + OUT_ABYTES;

#pragma unroll
        for (int ks = 0; ks < 8; ks++) {
            const int col = ks * 16;
            uint32_t aF[5][4];
#pragma unroll
            for (int mt = 0; mt < 5; mt++) {
                int row = mt * 16 + (lane & 15);
                ldmatrix_x4(aF[mt], aS + (row * OUT_AST + col + (lane >> 4) * 8) * 2);
            }
            uint32_t bF[2][2];
#pragma unroll
            for (int nt = 0; nt < 2; nt++) {
                int nrow = nbase + nt * 8 + (lane & 7);
                ldmatrix_x2(bF[nt], bS + (nrow * OUT_AST + col + ((lane & 15) >> 3) * 8) * 2);
            }
#pragma unroll
            for (int mt = 0; mt < 5; mt++)
#pragma unroll
                for (int nt = 0; nt < 2; nt++)
                    mma_bf16(acc[mt][nt], aF[mt], bF[nt]);
        }
        __syncthreads();
    }

    // Epilogue: bias + relu
#pragma unroll
    for (int mt = 0; mt < 5; mt++) {
        const int r0 = rowBase + mt * 16 + (lane >> 2);
        const int r1 = r0 + 8;
#pragma unroll
        for (int nt = 0; nt < 2; nt++) {
            const int c = nbase + nt * 8 + (lane & 3) * 2;
            const float b0 = bias[c], b1 = bias[c + 1];
            *(float2*)&out[(size_t)r0 * 128 + c] = make_float2(
                fmaxf(acc[mt][nt][0] + b0, 0.f), fmaxf(acc[mt][nt][1] + b1, 0.f));
            *(float2*)&out[(size_t)r1 * 128 + c] = make_float2(
                fmaxf(acc[mt][nt][2] + b0, 0.f), fmaxf(acc[mt][nt][3] + b1, 0.f));
        }
    }
}

// ===========================================================================
extern "C" void kernel_launch(void* const* d_in, const int* in_sizes, int n_in,
                              void* d_out, int out_size)
{
    const float* x     = (const float*)d_in[0];
    const int*   nbr   = (const int*)  d_in[1];
    const float* Wsum  = (const float*)d_in[2];
    const float* Wmean = (const float*)d_in[3];
    const float* Wmax  = (const float*)d_in[4];
    const float* Wmin  = (const float*)d_in[5];
    const float* W     = (const float*)d_in[6];
    const float* bias  = (const float*)d_in[7];
    float* out = (float*)d_out;

    const int CP_SMEM = 2 * 128 * CP_STRIDE * 2;  // 69,632 B
    cudaFuncSetAttribute(gemm_cp_mma_kernel,
                         cudaFuncAttributeMaxDynamicSharedMemorySize, CP_SMEM);
    cudaFuncSetAttribute(gemm_out_bsplit_kernel,
                         cudaFuncAttributeMaxDynamicSharedMemorySize, OUT_SMEM);

    // 0) conversions + weight splits
    prep_kernel<<<296, 256>>>(x, Wsum, Wmean, Wmax, Wmin, W);

    // 1) CP = 0.5 * Xb @ Wb^T (10000 x 1024), bf16 HMMA
    {
        dim3 grid(1024 / 128, (NN + 127) / 128);
        gemm_cp_mma_kernel<<<grid, 256, CP_SMEM>>>();
    }

    // 2) per-node aggregation -> A2 (split H)
    {
        dim3 grid((NN + 3) / 4);
        agg_kernel<<<grid, 128>>>(x, nbr);
    }

    // 3) out = relu(A2 @ B2^T + bias), bf16 HMMA split-precision
    gemm_out_bsplit_kernel<<<125, 256, OUT_SMEM>>>(bias, out);
}

// round 7
// speedup vs baseline: 2.3136x; 1.0667x over previous
#include <cuda_runtime.h>
#include <cuda_bf16.h>
#include <math_constants.h>
#include <cstdint>

#define NN   10000
#define FF   128
#define DEG  32
#define OUTF 128

// ---------------------------------------------------------------------------
// Scratch (__device__ globals; no allocation allowed)
// ---------------------------------------------------------------------------
__device__ float         g_C[(size_t)NN * 512];     // 0.5 * center projections, fp32
__device__ __nv_bfloat16 g_P[(size_t)NN * 512];     // 0.5 * neighbor projections, bf16
__device__ __nv_bfloat16 g_Xb[(size_t)NN * 128];    // X in bf16
__device__ __nv_bfloat16 g_Wb[(size_t)1024 * 128];  // Wbig transposed (for gemm_cp)
__device__ __nv_bfloat16 g_A2[(size_t)NN * 1536];   // H split: [2k]=hi,[2k+1]=lo (k<512); [1024+k]=hi
__device__ __nv_bfloat16 g_B2[(size_t)128 * 1536];  // W split: [2k]=[2k+1]=Whi; [1024+k]=Wlo

// ---------------------------------------------------------------------------
// Helpers
// ---------------------------------------------------------------------------
__device__ __forceinline__ uint32_t smem_u32(const void* p) {
    uint32_t a;
    asm("{ .reg .u64 t; cvta.to.shared.u64 t, %1; cvt.u32.u64 %0, t; }" : "=r"(a) : "l"(p));
    return a;
}
__device__ __forceinline__ void ldmatrix_x4(uint32_t* r, uint32_t addr) {
    asm volatile("ldmatrix.sync.aligned.m8n8.x4.shared.b16 {%0,%1,%2,%3}, [%4];"
                 : "=r"(r[0]), "=r"(r[1]), "=r"(r[2]), "=r"(r[3]) : "r"(addr));
}
__device__ __forceinline__ void ldmatrix_x2(uint32_t* r, uint32_t addr) {
    asm volatile("ldmatrix.sync.aligned.m8n8.x2.shared.b16 {%0,%1}, [%2];"
                 : "=r"(r[0]), "=r"(r[1]) : "r"(addr));
}
__device__ __forceinline__ void mma_bf16(float* c, const uint32_t* a, const uint32_t* b) {
    asm volatile(
        "mma.sync.aligned.m16n8k16.row.col.f32.bf16.bf16.f32 "
        "{%0,%1,%2,%3}, {%4,%5,%6,%7}, {%8,%9}, {%0,%1,%2,%3};"
        : "+f"(c[0]), "+f"(c[1]), "+f"(c[2]), "+f"(c[3])
        : "r"(a[0]), "r"(a[1]), "r"(a[2]), "r"(a[3]), "r"(b[0]), "r"(b[1]));
}
__device__ __forceinline__ void cp_async16(uint32_t smaddr, const void* gptr) {
    asm volatile("cp.async.ca.shared.global [%0], [%1], 16;"
                 :: "r"(smaddr), "l"(gptr) : "memory");
}
__device__ __forceinline__ uint32_t pack_bf2(__nv_bfloat16 a, __nv_bfloat16 b) {
    __nv_bfloat162 h; h.x = a; h.y = b;
    return *reinterpret_cast<uint32_t*>(&h);
}
__device__ __forceinline__ void bsplit(float v, __nv_bfloat16& hi, __nv_bfloat16& lo) {
    hi = __float2bfloat16_rn(v);
    lo = __float2bfloat16_rn(v - __bfloat162float(hi));
}

// ===========================================================================
// Kernel 0: prep — X->bf16; Wb (transposed Wbig, bf16); B2 (split W for out-GEMM)
// ===========================================================================
__global__ __launch_bounds__(256) void prep_kernel(
    const float* __restrict__ X,
    const float* __restrict__ Wsum, const float* __restrict__ Wmean,
    const float* __restrict__ Wmax, const float* __restrict__ Wmin,
    const float* __restrict__ W)
{
    const int tid = blockIdx.x * blockDim.x + threadIdx.x;
    const int stride = gridDim.x * blockDim.x;

    const float4* X4 = (const float4*)X;
    for (int v = tid; v < NN * 128 / 4; v += stride) {
        float4 f = X4[v];
        uint2 pk;
        pk.x = pack_bf2(__float2bfloat16_rn(f.x), __float2bfloat16_rn(f.y));
        pk.y = pack_bf2(__float2bfloat16_rn(f.z), __float2bfloat16_rn(f.w));
        *(uint2*)&g_Xb[(size_t)v * 4] = pk;
    }

    for (int v = tid; v < 1024 * 32; v += stride) {
        int n  = v >> 5;
        int k4 = (v & 31) * 4;
        int m  = (n >> 7) & 3;
        const float* __restrict__ Wm = (m == 0) ? Wsum : (m == 1) ? Wmean : (m == 2) ? Wmax : Wmin;
        int rowOff = (n >= 512) ? 128 : 0;
        int f = n & 127;
        float a0 = Wm[(rowOff + k4 + 0) * 128 + f];
        float a1 = Wm[(rowOff + k4 + 1) * 128 + f];
        float a2 = Wm[(rowOff + k4 + 2) * 128 + f];
        float a3 = Wm[(rowOff + k4 + 3) * 128 + f];
        uint2 pk;
        pk.x = pack_bf2(__float2bfloat16_rn(a0), __float2bfloat16_rn(a1));
        pk.y = pack_bf2(__float2bfloat16_rn(a2), __float2bfloat16_rn(a3));
        *(uint2*)&g_Wb[(size_t)n * 128 + k4] = pk;
    }

    // B2: [n][1536]: [2k]=[2k+1]=hi(W[k][n]); [1024+k]=lo
    for (int v = tid; v < 128 * 512; v += stride) {
        int n = v & 127;
        int k = v >> 7;
        float w = W[(size_t)k * 128 + n];
        __nv_bfloat16 hi, lo;
        bsplit(w, hi, lo);
        g_B2[(size_t)n * 1536 + 2 * k]     = hi;
        g_B2[(size_t)n * 1536 + 2 * k + 1] = hi;
        g_B2[(size_t)n * 1536 + 1024 + k]  = lo;
    }
}

// ===========================================================================
// Kernel 1: CP = 0.5 * (Xb @ Wb^T) via bf16 mma (M=10000, N=1024, K=128)
// CTA tile 128x128; 8 warps (4m x 2n), warp tile 32x64. cp.async loads.
// ===========================================================================
#define CP_STRIDE 136

__global__ __launch_bounds__(256) void gemm_cp_mma_kernel()
{
    extern __shared__ char smem[];
    __nv_bfloat16* Xs = (__nv_bfloat16*)smem;
    __nv_bfloat16* Ws = (__nv_bfloat16*)(smem + 128 * CP_STRIDE * 2);

    const int tid  = threadIdx.x;
    const int lane = tid & 31;
    const int wid  = tid >> 5;
    const int warpM = wid >> 1;
    const int warpN = wid & 1;

    const int nBase   = blockIdx.x * 128;
    const int rowBase = blockIdx.y * 128;

    const uint32_t sXsB = smem_u32(Xs);
    const uint32_t sWsB = smem_u32(Ws);

    // rows of X beyond NN: point at row 0 (garbage values, but row < 79*128+128
    // never exceeds... rowBase max = 78*128=9984, rows 9984..10111 -> clamp to 0;
    // results for those rows are discarded in the epilogue)
    for (int v = tid; v < 2048; v += 256) {
        int r = v >> 4, q = v & 15;
        int grow = rowBase + r;
        if (grow >= NN) grow = 0;
        cp_async16(sXsB + (r * CP_STRIDE + q * 8) * 2,
                   &g_Xb[(size_t)grow * 128 + q * 8]);
    }
    for (int v = tid; v < 2048; v += 256) {
        int n = v >> 4, q = v & 15;
        cp_async16(sWsB + (n * CP_STRIDE + q * 8) * 2,
                   &g_Wb[(size_t)(nBase + n) * 128 + q * 8]);
    }
    asm volatile("cp.async.commit_group;" ::: "memory");
    asm volatile("cp.async.wait_group 0;" ::: "memory");
    __syncthreads();

    float acc[2][8][4];
#pragma unroll
    for (int mt = 0; mt < 2; mt++)
#pragma unroll
        for (int nt = 0; nt < 8; nt++)
#pragma unroll
            for (int e = 0; e < 4; e++) acc[mt][nt][e] = 0.f;

#pragma unroll
    for (int kb = 0; kb < 128; kb += 16) {
        uint32_t aF[2][4];
#pragma unroll
        for (int mt = 0; mt < 2; mt++) {
            int row = warpM * 32 + mt * 16 + (lane & 15);
            int col = kb + (lane >> 4) * 8;
            ldmatrix_x4(aF[mt], sXsB + (row * CP_STRIDE + col) * 2);
        }
        uint32_t bF[8][2];
#pragma unroll
        for (int nt = 0; nt < 8; nt++) {
            int nrow = warpN * 64 + nt * 8 + (lane & 7);
            int col  = kb + ((lane & 15) >> 3) * 8;
            ldmatrix_x2(bF[nt], sWsB + (nrow * CP_STRIDE + col) * 2);
        }
#pragma unroll
        for (int mt = 0; mt < 2; mt++)
#pragma unroll
            for (int nt = 0; nt < 8; nt++)
                mma_bf16(acc[mt][nt], aF[mt], bF[nt]);
    }

    // Epilogue: store 0.5*value (folds sigmoid's a/2 into the projections)
#pragma unroll
    for (int mt = 0; mt < 2; mt++) {
        const int r0 = rowBase + warpM * 32 + mt * 16 + (lane >> 2);
        const int r1 = r0 + 8;
#pragma unroll
        for (int nt = 0; nt < 8; nt++) {
            const int cLoc = warpN * 64 + nt * 8 + (lane & 3) * 2;
            const int cAbs = nBase + cLoc;
            float v00 = 0.5f * acc[mt][nt][0], v01 = 0.5f * acc[mt][nt][1];
            float v10 = 0.5f * acc[mt][nt][2], v11 = 0.5f * acc[mt][nt][3];
            if (cAbs < 512) {
                if (r0 < NN) *(float2*)&g_C[(size_t)r0 * 512 + cAbs] = make_float2(v00, v01);
                if (r1 < NN) *(float2*)&g_C[(size_t)r1 * 512 + cAbs] = make_float2(v10, v11);
            } else {
                const int cP = cAbs - 512;
                if (r0 < NN)
                    *(uint32_t*)&g_P[(size_t)r0 * 512 + cP] =
                        pack_bf2(__float2bfloat16_rn(v00), __float2bfloat16_rn(v01));
                if (r1 < NN)
                    *(uint32_t*)&g_P[(size_t)r1 * 512 + cP] =
                        pack_bf2(__float2bfloat16_rn(v10), __float2bfloat16_rn(v11));
            }
        }
    }
}

// ===========================================================================
// Kernel 2: per-node aggregation -> A2 (bf16 hi/lo split of H)
// ===========================================================================
__device__ __forceinline__ float tanha(float a) {
    float t;
    asm("tanh.approx.f32 %0, %1;" : "=f"(t) : "f"(a));
    return t;
}
__device__ __forceinline__ float4 add4(float4 a, float4 b) {
    return make_float4(a.x + b.x, a.y + b.y, a.z + b.z, a.w + b.w);
}
__device__ __forceinline__ float4 max4(float4 a, float4 b) {
    return make_float4(fmaxf(a.x, b.x), fmaxf(a.y, b.y), fmaxf(a.z, b.z), fmaxf(a.w, b.w));
}
__device__ __forceinline__ float4 min4(float4 a, float4 b) {
    return make_float4(fminf(a.x, b.x), fminf(a.y, b.y), fminf(a.z, b.z), fminf(a.w, b.w));
}
__device__ __forceinline__ float4 loadP4(const __nv_bfloat16* __restrict__ p) {
    uint2 pk = *(const uint2*)p;
    __nv_bfloat162 h0 = *reinterpret_cast<__nv_bfloat162*>(&pk.x);
    __nv_bfloat162 h1 = *reinterpret_cast<__nv_bfloat162*>(&pk.y);
    float2 f0 = __bfloat1622float2(h0);
    float2 f1 = __bfloat1622float2(h1);
    return make_float4(f0.x, f0.y, f1.x, f1.y);
}
__device__ __forceinline__ float4 sigmul4(float4 c, float4 p, float4 hx) {
    return make_float4(fmaf(tanha(c.x + p.x), hx.x, hx.x),
                       fmaf(tanha(c.y + p.y), hx.y, hx.y),
                       fmaf(tanha(c.z + p.z), hx.z, hx.z),
                       fmaf(tanha(c.w + p.w), hx.w, hx.w));
}
__device__ __forceinline__ void store_split_group(
    __nv_bfloat16* a2, int koff, float4 v)
{
    __nv_bfloat16 h0, l0, h1, l1, h2, l2, h3, l3;
    bsplit(v.x, h0, l0); bsplit(v.y, h1, l1);
    bsplit(v.z, h2, l2); bsplit(v.w, h3, l3);
    uint4 pk;
    pk.x = pack_bf2(h0, l0); pk.y = pack_bf2(h1, l1);
    pk.z = pack_bf2(h2, l2); pk.w = pack_bf2(h3, l3);
    *(uint4*)&a2[2 * koff] = pk;
    uint2 t;
    t.x = pack_bf2(h0, h1); t.y = pack_bf2(h2, h3);
    *(uint2*)&a2[1024 + koff] = t;
}

__global__ __launch_bounds__(128) void agg_kernel(
    const float* __restrict__ x, const int* __restrict__ nbr)
{
    const int warp = threadIdx.x >> 5;
    const int lane = threadIdx.x & 31;
    const int i = blockIdx.x * 4 + warp;
    if (i >= NN) return;

    const int jl = nbr[i * DEG + lane];

    const float4* __restrict__ x4 = (const float4*)x;
    const float4* __restrict__ C4 = (const float4*)g_C;

    const float4 xi = x4[i * 32 + lane];
    const size_t cb = (size_t)i * 128;
    const float4 c0 = C4[cb + 0  + lane];
    const float4 c1 = C4[cb + 32 + lane];
    const float4 c2 = C4[cb + 64 + lane];
    const float4 c3 = C4[cb + 96 + lane];

    float4 s0 = make_float4(0.f, 0.f, 0.f, 0.f);
    float4 s1 = make_float4(0.f, 0.f, 0.f, 0.f);
    float4 s2 = make_float4(-CUDART_INF_F, -CUDART_INF_F, -CUDART_INF_F, -CUDART_INF_F);
    float4 s3 = make_float4( CUDART_INF_F,  CUDART_INF_F,  CUDART_INF_F,  CUDART_INF_F);

#pragma unroll 4
    for (int d = 0; d < DEG; d++) {
        const int j = __shfl_sync(0xffffffffu, jl, d);
        const float4 xj = x4[j * 32 + lane];
        const float4 hx = make_float4(0.5f * xj.x, 0.5f * xj.y, 0.5f * xj.z, 0.5f * xj.w);
        const __nv_bfloat16* __restrict__ prow = &g_P[(size_t)j * 512 + lane * 4];
        const float4 p0 = loadP4(prow + 0);
        const float4 p1 = loadP4(prow + 128);
        const float4 p2 = loadP4(prow + 256);
        const float4 p3 = loadP4(prow + 384);

        s0 = add4(s0, sigmul4(c0, p0, hx));
        s1 = add4(s1, sigmul4(c1, p1, hx));
        s2 = max4(s2, sigmul4(c2, p2, hx));
        s3 = min4(s3, sigmul4(c3, p3, hx));
    }

    const float inv_deg = 1.0f / (float)DEG;
    float4 h0 = add4(xi, s0);
    float4 h1 = add4(xi, make_float4(s1.x * inv_deg, s1.y * inv_deg,
                                     s1.z * inv_deg, s1.w * inv_deg));
    float4 h2 = add4(xi, s2);
    float4 h3 = add4(xi, s3);

    __nv_bfloat16* a2 = &g_A2[(size_t)i * 1536];
    store_split_group(a2, 0   + lane * 4, h0);
    store_split_group(a2, 128 + lane * 4, h1);
    store_split_group(a2, 256 + lane * 4, h2);
    store_split_group(a2, 384 + lane * 4, h3);
}

// ===========================================================================
// Kernel 3: out = relu(A2 @ B2^T + bias)  (M=10000, N=128, K=1536, bf16 HMMA)
// Tile M=80 x N=64 -> grid (125, 2) = 250 CTAs, 2 CTAs/SM co-resident.
// 128 threads (4 warps); warp tile 80x16 (mt=5, nt=2). 2-stage cp.async, BK=128.
// ===========================================================================
#define OUT_NKB    12
#define OUT_AST    136                      // smem row stride (bf16 elems)
#define OUT_ABYTES (80 * OUT_AST * 2)       // 21760
#define OUT_BBYTES (64 * OUT_AST * 2)       // 17408
#define OUT_STAGE  (OUT_ABYTES + OUT_BBYTES)
#define OUT_SMEM   (2 * OUT_STAGE)          // 78336

__global__ __launch_bounds__(128) void gemm_out_bsplit_kernel(
    const float* __restrict__ bias, float* __restrict__ out)
{
    extern __shared__ char smem[];
    const uint32_t sbase = smem_u32(smem);
    const int tid  = threadIdx.x;
    const int lane = tid & 31;
    const int wid  = tid >> 5;
    const int rowBase   = blockIdx.x * 80;
    const int nTileBase = blockIdx.y * 64;
    const int nbase     = wid * 16;          // local within the 64-wide tile

    float acc[5][2][4];
#pragma unroll
    for (int mt = 0; mt < 5; mt++)
#pragma unroll
        for (int nt = 0; nt < 2; nt++)
#pragma unroll
            for (int e = 0; e < 4; e++) acc[mt][nt][e] = 0.f;

    // ---- async load of one K-chunk (128 elems = 16 quads per row) into stage s ----
    auto issue = [&](int kb, int s) {
        const uint32_t abase = sbase + s * OUT_STAGE;
        for (int v = tid; v < 1280; v += 128) {         // A: 80 rows x 16 quads
            int r = v >> 4, q = v & 15;
            cp_async16(abase + (r * OUT_AST + q * 8) * 2,
                       &g_A2[(size_t)(rowBase + r) * 1536 + kb * 128 + q * 8]);
        }
        const uint32_t bbase = abase + OUT_ABYTES;
        for (int v = tid; v < 1024; v += 128) {         // B: 64 rows x 16 quads
            int n = v >> 4, q = v & 15;
            cp_async16(bbase + (n * OUT_AST + q * 8) * 2,
                       &g_B2[(size_t)(nTileBase + n) * 1536 + kb * 128 + q * 8]);
        }
        asm volatile("cp.async.commit_group;" ::: "memory");
    };

    issue(0, 0);

#pragma unroll
    for (int kb = 0; kb < OUT_NKB; kb++) {
        if (kb + 1 < OUT_NKB) {
            issue(kb + 1, (kb + 1) & 1);
            asm volatile("cp.async.wait_group 1;" ::: "memory");
        } else {
            asm volatile("cp.async.wait_group 0;" ::: "memory");
        }
        __syncthreads();

        const uint32_t aS = sbase + (kb & 1) * OUT_STAGE;
        const uint32_t bS = aS + OUT_ABYTES;

#pragma unroll
        for (int ks = 0; ks < 8; ks++) {
            const int col = ks * 16;
            uint32_t aF[5][4];
#pragma unroll
            for (int mt = 0; mt < 5; mt++) {
                int row = mt * 16 + (lane & 15);
                ldmatrix_x4(aF[mt], aS + (row * OUT_AST + col + (lane >> 4) * 8) * 2);
            }
            uint32_t bF[2][2];
#pragma unroll
            for (int nt = 0; nt < 2; nt++) {
                int nrow = nbase + nt * 8 + (lane & 7);
                ldmatrix_x2(bF[nt], bS + (nrow * OUT_AST + col + ((lane & 15) >> 3) * 8) * 2);
            }
#pragma unroll
            for (int mt = 0; mt < 5; mt++)
#pragma unroll
                for (int nt = 0; nt < 2; nt++)
                    mma_bf16(acc[mt][nt], aF[mt], bF[nt]);
        }
        __syncthreads();
    }

    // Epilogue: bias + relu
#pragma unroll
    for (int mt = 0; mt < 5; mt++) {
        const int r0 = rowBase + mt * 16 + (lane >> 2);
        const int r1 = r0 + 8;
#pragma unroll
        for (int nt = 0; nt < 2; nt++) {
            const int c = nTileBase + nbase + nt * 8 + (lane & 3) * 2;
            const float b0 = bias[c], b1 = bias[c + 1];
            *(float2*)&out[(size_t)r0 * 128 + c] = make_float2(
                fmaxf(acc[mt][nt][0] + b0, 0.f), fmaxf(acc[mt][nt][1] + b1, 0.f));
            *(float2*)&out[(size_t)r1 * 128 + c] = make_float2(
                fmaxf(acc[mt][nt][2] + b0, 0.f), fmaxf(acc[mt][nt][3] + b1, 0.f));
        }
    }
}

// ===========================================================================
extern "C" void kernel_launch(void* const* d_in, const int* in_sizes, int n_in,
                              void* d_out, int out_size)
{
    const float* x     = (const float*)d_in[0];
    const int*   nbr   = (const int*)  d_in[1];
    const float* Wsum  = (const float*)d_in[2];
    const float* Wmean = (const float*)d_in[3];
    const float* Wmax  = (const float*)d_in[4];
    const float* Wmin  = (const float*)d_in[5];
    const float* W     = (const float*)d_in[6];
    const float* bias  = (const float*)d_in[7];
    float* out = (float*)d_out;

    const int CP_SMEM = 2 * 128 * CP_STRIDE * 2;  // 69,632 B
    cudaFuncSetAttribute(gemm_cp_mma_kernel,
                         cudaFuncAttributeMaxDynamicSharedMemorySize, CP_SMEM);
    cudaFuncSetAttribute(gemm_out_bsplit_kernel,
                         cudaFuncAttributeMaxDynamicSharedMemorySize, OUT_SMEM);

    // 0) conversions + weight splits
    prep_kernel<<<296, 256>>>(x, Wsum, Wmean, Wmax, Wmin, W);

    // 1) CP = 0.5 * Xb @ Wb^T (10000 x 1024), bf16 HMMA
    {
        dim3 grid(1024 / 128, (NN + 127) / 128);
        gemm_cp_mma_kernel<<<grid, 256, CP_SMEM>>>();
    }

    // 2) per-node aggregation -> A2 (split H)
    {
        dim3 grid((NN + 3) / 4);
        agg_kernel<<<grid, 128>>>(x, nbr);
    }

    // 3) out = relu(A2 @ B2^T + bias), bf16 HMMA split-precision
    {
        dim3 grid(125, 2);
        gemm_out_bsplit_kernel<<<grid, 128, OUT_SMEM>>>(bias, out);
    }
}